// round 9
// baseline (speedup 1.0000x reference)
#include <cuda_runtime.h>

typedef unsigned long long u64;

__device__ __forceinline__ u64 pack2(float lo, float hi) {
    u64 r; asm("mov.b64 %0, {%1, %2};" : "=l"(r) : "f"(lo), "f"(hi)); return r;
}
__device__ __forceinline__ void unpack2(u64 v, float& lo, float& hi) {
    asm("mov.b64 {%0, %1}, %2;" : "=f"(lo), "=f"(hi) : "l"(v));
}
__device__ __forceinline__ u64 ffma2(u64 a, u64 b, u64 c) {
    u64 d; asm("fma.rn.f32x2 %0, %1, %2, %3;" : "=l"(d) : "l"(a), "l"(b), "l"(c)); return d;
}
__device__ __forceinline__ void red4(float* addr, float a, float b, float c, float d) {
    asm volatile("red.global.add.v4.f32 [%0], {%1, %2, %3, %4};"
                 :: "l"(addr), "f"(a), "f"(b), "f"(c), "f"(d) : "memory");
}

#define BB 16
#define NPIX 1024
#define DD 128
#define KK 32
#define CHUNKS 32
#define ROWS_CTA 32          // NPIX / CHUNKS
#define NTHREADS 256
#define NWARPS 8
#define CWS 132              // codeword smem row stride (conflict-free float4)

__global__ void zero_kernel(float4* out, int n4) {
    int i = blockIdx.x * blockDim.x + threadIdx.x;
    if (i < n4) out[i] = make_float4(0.f, 0.f, 0.f, 0.f);
}

__global__ void __launch_bounds__(NTHREADS, 4) enc_kernel(
    const float* __restrict__ x, const float* __restrict__ cw,
    const float* __restrict__ scale, float* __restrict__ out)
{
    __shared__ __align__(16) float cw_s[KK * CWS];
    __shared__ __align__(16) float x_s[ROWS_CTA * DD];
    __shared__ float A_s[ROWS_CTA * KK];
    __shared__ float S_s[NWARPS * KK];

    const int t = threadIdx.x;
    const int lane = t & 31;
    const int w = t >> 5;
    const int b = blockIdx.y;
    const int chunk = blockIdx.x;

    // ---- stage: x first (DRAM-latency loads), then codewords (L2 hits).
    //      x2 for this warp's 4 rows comes free from the load registers.
    float x2[4];
    {
        const float4* xg = (const float4*)(x + ((size_t)b * NPIX + chunk * ROWS_CTA) * DD);
        float4* xs4 = (float4*)x_s;
        #pragma unroll
        for (int p = 0; p < 4; p++) {
            // f4 index p*256+t -> row = 8p + w, col4 = lane  (this warp's rows)
            float4 v = xg[p * NTHREADS + t];
            xs4[p * NTHREADS + t] = v;
            float q = v.x * v.x;
            q = fmaf(v.y, v.y, q);
            q = fmaf(v.z, v.z, q);
            x2[p] = fmaf(v.w, v.w, q);
        }
        const float4* cg = (const float4*)cw;
        #pragma unroll
        for (int i = t; i < KK * DD / 4; i += NTHREADS) {
            int k = i >> 5, d4 = i & 31;
            *(float4*)&cw_s[k * CWS + d4 * 4] = cg[i];
        }
        // 4 interleaved butterfly reductions for x2
        #pragma unroll
        for (int off = 16; off > 0; off >>= 1) {
            #pragma unroll
            for (int p = 0; p < 4; p++) x2[p] += __shfl_xor_sync(0xffffffffu, x2[p], off);
        }
    }
    const float sc = scale[lane];
    __syncthreads();

    // ---- dot phase: warp w rows {w, w+8, w+16, w+24}; lane = codeword k.
    //      cv (conflict-free LDS.128) software-pipelined one iteration ahead.
    u64 da[8];
    u64 c2a = 0ull, c2b = 0ull;
    #pragma unroll
    for (int j = 0; j < 8; j++) da[j] = 0ull;
    const ulonglong2* cp = (const ulonglong2*)&cw_s[lane * CWS];
    {
        ulonglong2 cv = cp[0];
        #pragma unroll
        for (int i = 0; i < DD / 4; i++) {
            ulonglong2 cvn;
            if (i + 1 < DD / 4) cvn = cp[i + 1];
            c2a = ffma2(cv.x, cv.x, c2a);
            c2b = ffma2(cv.y, cv.y, c2b);
            #pragma unroll
            for (int j = 0; j < 4; j++) {
                ulonglong2 xv = *(const ulonglong2*)&x_s[(8 * j + w) * DD + 4 * i];
                da[2 * j]     = ffma2(xv.x, cv.x, da[2 * j]);
                da[2 * j + 1] = ffma2(xv.y, cv.y, da[2 * j + 1]);
            }
            cv = cvn;
        }
    }
    float c2r;
    {
        float l0, h0, l1, h1;
        unpack2(c2a, l0, h0); unpack2(c2b, l1, h1);
        c2r = (l0 + h0) + (l1 + h1);
    }
    const float sc2 = sc * c2r;       // sc * ||c||^2
    const float scm2 = -2.f * sc;     // -2 * sc

    // ---- softmax over K=32 lanes (no max-subtraction: scale<0, logits bounded;
    //      validated at rel_err ~2.5e-7 across rounds) ----
    float e[4], s[4];
    #pragma unroll
    for (int j = 0; j < 4; j++) {
        float l0, h0, l1, h1;
        unpack2(da[2 * j], l0, h0);
        unpack2(da[2 * j + 1], l1, h1);
        float xc = (l0 + h0) + (l1 + h1);
        float sl = fmaf(sc, x2[j], fmaf(scm2, xc, sc2));
        e[j] = __expf(sl);
        s[j] = e[j];
    }
    #pragma unroll
    for (int off = 16; off > 0; off >>= 1) {
        #pragma unroll
        for (int j = 0; j < 4; j++) s[j] += __shfl_xor_sync(0xffffffffu, s[j], off);
    }
    float sA = 0.f;
    #pragma unroll
    for (int j = 0; j < 4; j++) {
        float a = e[j] * __fdividef(1.f, s[j]);
        A_s[(8 * j + w) * KK + lane] = a;
        sA += a;
    }
    S_s[w * KK + lane] = sA;
    __syncthreads();

    // Sk reduction issued BEFORE the E loop so its LDS latency overlaps compute
    float Sk = 0.f;
    #pragma unroll
    for (int r = 0; r < NWARPS; r++) Sk += S_s[r * KK + lane];

    // ---- E accumulate: k = lane, d slab = [w*16, w*16+16); pipelined ----
    u64 acc[8];
    #pragma unroll
    for (int j = 0; j < 8; j++) acc[j] = 0ull;
    {
        float av = A_s[lane];
        ulonglong2 xv0 = *(const ulonglong2*)&x_s[w * 16];
        ulonglong2 xv1 = *(const ulonglong2*)&x_s[w * 16 + 4];
        #pragma unroll
        for (int r = 0; r < ROWS_CTA; r++) {
            float avn;
            ulonglong2 nv0, nv1;
            if (r + 1 < ROWS_CTA) {
                avn = A_s[(r + 1) * KK + lane];
                nv0 = *(const ulonglong2*)&x_s[(r + 1) * DD + w * 16];
                nv1 = *(const ulonglong2*)&x_s[(r + 1) * DD + w * 16 + 4];
            }
            u64 pa = pack2(av, av);
            acc[0] = ffma2(pa, xv0.x, acc[0]);
            acc[1] = ffma2(pa, xv0.y, acc[1]);
            acc[2] = ffma2(pa, xv1.x, acc[2]);
            acc[3] = ffma2(pa, xv1.y, acc[3]);
            // second half of the 16-float slab
            ulonglong2 yv0 = *(const ulonglong2*)&x_s[r * DD + w * 16 + 8];
            ulonglong2 yv1 = *(const ulonglong2*)&x_s[r * DD + w * 16 + 12];
            acc[4] = ffma2(pa, yv0.x, acc[4]);
            acc[5] = ffma2(pa, yv0.y, acc[5]);
            acc[6] = ffma2(pa, yv1.x, acc[6]);
            acc[7] = ffma2(pa, yv1.y, acc[7]);
            av = avn; xv0 = nv0; xv1 = nv1;
        }
    }
    const float nSk = -Sk;

    float accf[16];
    #pragma unroll
    for (int j = 0; j < 8; j++) unpack2(acc[j], accf[2 * j], accf[2 * j + 1]);

    // ---- epilogue: E += acc - Sk*c, vector reduction straight to out ----
    float* ob = out + ((size_t)(b * KK + lane)) * DD + w * 16;
    const float* cr = &cw_s[lane * CWS + w * 16];
    #pragma unroll
    for (int j = 0; j < 4; j++) {
        red4(&ob[4 * j],
             fmaf(nSk, cr[4 * j + 0], accf[4 * j + 0]),
             fmaf(nSk, cr[4 * j + 1], accf[4 * j + 1]),
             fmaf(nSk, cr[4 * j + 2], accf[4 * j + 2]),
             fmaf(nSk, cr[4 * j + 3], accf[4 * j + 3]));
    }
}

extern "C" void kernel_launch(void* const* d_in, const int* in_sizes, int n_in,
                              void* d_out, int out_size) {
    const float* x  = (const float*)d_in[0];
    const float* cw = (const float*)d_in[1];
    const float* sc = (const float*)d_in[2];
    float* out = (float*)d_out;

    int n4 = out_size / 4;                 // 16384 float4
    zero_kernel<<<(n4 + 255) / 256, 256>>>((float4*)out, n4);

    dim3 grid(CHUNKS, BB);
    enc_kernel<<<grid, NTHREADS>>>(x, cw, sc, out);
}

// round 11
// speedup vs baseline: 1.1767x; 1.1767x over previous
#include <cuda_runtime.h>
#include <cstdint>

typedef unsigned long long u64;

__device__ __forceinline__ u64 pack2(float lo, float hi) {
    u64 r; asm("mov.b64 %0, {%1, %2};" : "=l"(r) : "f"(lo), "f"(hi)); return r;
}
__device__ __forceinline__ void unpack2(u64 v, float& lo, float& hi) {
    asm("mov.b64 {%0, %1}, %2;" : "=f"(lo), "=f"(hi) : "l"(v));
}
__device__ __forceinline__ u64 ffma2(u64 a, u64 b, u64 c) {
    u64 d; asm("fma.rn.f32x2 %0, %1, %2, %3;" : "=l"(d) : "l"(a), "l"(b), "l"(c)); return d;
}
__device__ __forceinline__ void red4(float* addr, float a, float b, float c, float d) {
    asm volatile("red.global.add.v4.f32 [%0], {%1, %2, %3, %4};"
                 :: "l"(addr), "f"(a), "f"(b), "f"(c), "f"(d) : "memory");
}
__device__ __forceinline__ uint32_t tf32c(float f) {
    uint32_t u; asm("cvt.rna.tf32.f32 %0, %1;" : "=r"(u) : "f"(f)); return u;
}
// D(16x8) += A(16x8,row) * B(8x8,col)  [tf32, fp32 accum]
__device__ __forceinline__ void mma8(float d[4],
    uint32_t a0, uint32_t a1, uint32_t a2, uint32_t a3, uint32_t b0, uint32_t b1) {
    asm volatile("mma.sync.aligned.m16n8k8.row.col.f32.tf32.tf32.f32 "
        "{%0,%1,%2,%3}, {%4,%5,%6,%7}, {%8,%9}, {%0,%1,%2,%3};"
        : "+f"(d[0]), "+f"(d[1]), "+f"(d[2]), "+f"(d[3])
        : "r"(a0), "r"(a1), "r"(a2), "r"(a3), "r"(b0), "r"(b1));
}

#define BB 16
#define NPIX 1024
#define DD 128
#define KK 32
#define CHUNKS 8
#define ROWS_CTA 128
#define NTHREADS 512
#define STR 132              // padded row stride (floats): conflict-free frag loads

// dynamic smem layout (bytes)
#define O_XH 0               // tf32 x  [128][132]            67584
#define O_XF 67584           // fp32 x  [128][132]            67584
#define O_CH 135168          // tf32 c-hi [32][132]           16896
#define O_CL 152064          // tf32 c-lo [32][132]           16896
#define O_AS 168960          // A (exp then normalized) [128][33]  16896
#define O_X2 185856          // x2 [128]                      512
#define O_PS 186368          // row-sum halves [128][2]       1024
#define O_P1 187392          // scale[k]                      128
#define O_P2 187520          // -2*scale[k]                   128
#define O_P3 187648          // scale[k]*c2[k]                128
#define SMEM_TOTAL 187776

__global__ void zero_kernel(float4* out, int n4) {
    int i = blockIdx.x * blockDim.x + threadIdx.x;
    if (i < n4) out[i] = make_float4(0.f, 0.f, 0.f, 0.f);
}

__global__ void __launch_bounds__(NTHREADS) enc_kernel(
    const float* __restrict__ x, const float* __restrict__ cw,
    const float* __restrict__ scale, float* __restrict__ out)
{
    extern __shared__ __align__(16) char sm[];
    uint32_t* XH = (uint32_t*)(sm + O_XH);
    float*    XF = (float*)(sm + O_XF);
    uint32_t* CH = (uint32_t*)(sm + O_CH);
    uint32_t* CL = (uint32_t*)(sm + O_CL);
    float*    As = (float*)(sm + O_AS);
    float*    x2s = (float*)(sm + O_X2);
    float*    ps = (float*)(sm + O_PS);
    float*    p1 = (float*)(sm + O_P1);
    float*    p2 = (float*)(sm + O_P2);
    float*    p3 = (float*)(sm + O_P3);

    const int t = threadIdx.x, lane = t & 31, w = t >> 5;   // w: 0..15
    const int b = blockIdx.y, chunk = blockIdx.x;

    // ================= stage: x (fp32 + tf32) and c (tf32 hi/lo) =================
    {
        const float4* xg = (const float4*)(x + ((size_t)b * NPIX + chunk * ROWS_CTA) * DD);
        float q[8];
        #pragma unroll
        for (int p = 0; p < 8; p++) {
            float4 v = xg[p * NTHREADS + t];           // row = 16p + w, col = 4*lane
            int off = (16 * p + w) * STR + 4 * lane;
            *(float4*)&XF[off] = v;
            uint4 h;
            h.x = tf32c(v.x); h.y = tf32c(v.y); h.z = tf32c(v.z); h.w = tf32c(v.w);
            *(uint4*)&XH[off] = h;
            float s = v.x * v.x; s = fmaf(v.y, v.y, s);
            s = fmaf(v.z, v.z, s); q[p] = fmaf(v.w, v.w, s);
        }
        const float4* cg = (const float4*)cw;
        float qc[2];
        #pragma unroll
        for (int p = 0; p < 2; p++) {
            float4 v = cg[p * NTHREADS + t];           // k = 16p + w, col = 4*lane
            int off = (16 * p + w) * STR + 4 * lane;
            uint4 h, l;
            h.x = tf32c(v.x); h.y = tf32c(v.y); h.z = tf32c(v.z); h.w = tf32c(v.w);
            l.x = tf32c(v.x - __uint_as_float(h.x));
            l.y = tf32c(v.y - __uint_as_float(h.y));
            l.z = tf32c(v.z - __uint_as_float(h.z));
            l.w = tf32c(v.w - __uint_as_float(h.w));
            *(uint4*)&CH[off] = h;
            *(uint4*)&CL[off] = l;
            float s = v.x * v.x; s = fmaf(v.y, v.y, s);
            s = fmaf(v.z, v.z, s); qc[p] = fmaf(v.w, v.w, s);
        }
        #pragma unroll
        for (int off = 16; off > 0; off >>= 1) {
            #pragma unroll
            for (int p = 0; p < 8; p++) q[p] += __shfl_xor_sync(0xffffffffu, q[p], off);
            #pragma unroll
            for (int p = 0; p < 2; p++) qc[p] += __shfl_xor_sync(0xffffffffu, qc[p], off);
        }
        if (lane == 0) {
            #pragma unroll
            for (int p = 0; p < 8; p++) x2s[16 * p + w] = q[p];
            #pragma unroll
            for (int p = 0; p < 2; p++) {
                int k = 16 * p + w;
                float s = scale[k];
                p1[k] = s; p2[k] = -2.f * s; p3[k] = s * qc[p];
            }
        }
    }
    __syncthreads();

    // ========== dot phase: 3xTF32 mma. warp = (row-tile rt, k-half kh) ==========
    // warp tile: rows [16rt,16rt+16), k in [16kh,16kh+16) as n-tiles {2kh,2kh+1}
    {
        const int rt = w & 7, kh = w >> 3;
        const int gid = lane >> 2, tig = lane & 3;
        const int r0 = 16 * rt + gid, r1 = r0 + 8;
        const uint32_t* xh0 = &XH[r0 * STR];
        const uint32_t* xh1 = &XH[r1 * STR];
        const float*    xf0 = &XF[r0 * STR];
        const float*    xf1 = &XF[r1 * STR];

        float d0[4] = {0.f, 0.f, 0.f, 0.f};
        float d1[4] = {0.f, 0.f, 0.f, 0.f};
        const int kb0 = 8 * (2 * kh) + gid;       // codeword row for n-tile 0
        const int kb1 = 8 * (2 * kh + 1) + gid;   // codeword row for n-tile 1

        #pragma unroll
        for (int c = 0; c < 16; c++) {
            const int cb = c * 8;
            // A fragments (hi from smem, lo computed: exact residual, re-rounded)
            uint32_t ah0 = xh0[cb + tig],     ah1 = xh1[cb + tig];
            uint32_t ah2 = xh0[cb + tig + 4], ah3 = xh1[cb + tig + 4];
            uint32_t al0 = tf32c(xf0[cb + tig]     - __uint_as_float(ah0));
            uint32_t al1 = tf32c(xf1[cb + tig]     - __uint_as_float(ah1));
            uint32_t al2 = tf32c(xf0[cb + tig + 4] - __uint_as_float(ah2));
            uint32_t al3 = tf32c(xf1[cb + tig + 4] - __uint_as_float(ah3));
            // B fragments, n-tile 0
            uint32_t bh0 = CH[kb0 * STR + cb + tig], bh1 = CH[kb0 * STR + cb + tig + 4];
            uint32_t bl0 = CL[kb0 * STR + cb + tig], bl1 = CL[kb0 * STR + cb + tig + 4];
            mma8(d0, ah0, ah1, ah2, ah3, bh0, bh1);
            mma8(d0, ah0, ah1, ah2, ah3, bl0, bl1);
            mma8(d0, al0, al1, al2, al3, bh0, bh1);
            // B fragments, n-tile 1
            bh0 = CH[kb1 * STR + cb + tig]; bh1 = CH[kb1 * STR + cb + tig + 4];
            bl0 = CL[kb1 * STR + cb + tig]; bl1 = CL[kb1 * STR + cb + tig + 4];
            mma8(d1, ah0, ah1, ah2, ah3, bh0, bh1);
            mma8(d1, ah0, ah1, ah2, ah3, bl0, bl1);
            mma8(d1, al0, al1, al2, al3, bh0, bh1);
        }

        // ---- exp + half-row sums (no max-subtraction: scale<0, logits bounded;
        //      validated rel_err ~2.5e-7 across rounds) ----
        const float x20 = x2s[r0], x21 = x2s[r1];
        float s0 = 0.f, s1 = 0.f;
        #pragma unroll
        for (int tt = 0; tt < 2; tt++) {
            const float* D = tt ? d1 : d0;
            #pragma unroll
            for (int p = 0; p < 2; p++) {
                int k = 8 * (2 * kh + tt) + 2 * tig + p;
                float P1 = p1[k], P2 = p2[k], P3 = p3[k];
                float e0 = __expf(fmaf(P1, x20, fmaf(P2, D[p],     P3)));
                float e1 = __expf(fmaf(P1, x21, fmaf(P2, D[2 + p], P3)));
                As[r0 * 33 + k] = e0;
                As[r1 * 33 + k] = e1;
                s0 += e0; s1 += e1;
            }
        }
        s0 += __shfl_xor_sync(0xffffffffu, s0, 1);
        s0 += __shfl_xor_sync(0xffffffffu, s0, 2);
        s1 += __shfl_xor_sync(0xffffffffu, s1, 1);
        s1 += __shfl_xor_sync(0xffffffffu, s1, 2);
        if (tig == 0) { ps[r0 * 2 + kh] = s0; ps[r1 * 2 + kh] = s1; }
    }
    __syncthreads();

    // ================= normalize A in place =================
    #pragma unroll
    for (int j = 0; j < 8; j++) {
        int r = 16 * j + w;
        float rinv = __fdividef(1.f, ps[2 * r] + ps[2 * r + 1]);
        As[r * 33 + lane] *= rinv;
    }
    __syncthreads();

    // ================= E accumulate: k = lane, d slab [8w, 8w+8) =================
    u64 acc[4] = {0ull, 0ull, 0ull, 0ull};
    float Sk = 0.f;
    #pragma unroll 4
    for (int r = 0; r < ROWS_CTA; r++) {
        float av = As[r * 33 + lane];
        Sk += av;
        u64 pa = pack2(av, av);
        const ulonglong2* xp = (const ulonglong2*)&XF[r * STR + 8 * w];
        ulonglong2 v0 = xp[0], v1 = xp[1];
        acc[0] = ffma2(pa, v0.x, acc[0]);
        acc[1] = ffma2(pa, v0.y, acc[1]);
        acc[2] = ffma2(pa, v1.x, acc[2]);
        acc[3] = ffma2(pa, v1.y, acc[3]);
    }
    const float nSk = -Sk;

    float a[8];
    #pragma unroll
    for (int j = 0; j < 4; j++) unpack2(acc[j], a[2 * j], a[2 * j + 1]);

    // codewords for the correction read from global (L2-hot, 16KB total)
    const float4* cg4 = (const float4*)(cw + (size_t)lane * DD + 8 * w);
    float4 c0 = cg4[0], c1 = cg4[1];
    float* ob = out + ((size_t)(b * KK + lane)) * DD + 8 * w;
    red4(ob, fmaf(nSk, c0.x, a[0]), fmaf(nSk, c0.y, a[1]),
             fmaf(nSk, c0.z, a[2]), fmaf(nSk, c0.w, a[3]));
    red4(ob + 4, fmaf(nSk, c1.x, a[4]), fmaf(nSk, c1.y, a[5]),
                 fmaf(nSk, c1.z, a[6]), fmaf(nSk, c1.w, a[7]));
}

extern "C" void kernel_launch(void* const* d_in, const int* in_sizes, int n_in,
                              void* d_out, int out_size) {
    const float* x  = (const float*)d_in[0];
    const float* cw = (const float*)d_in[1];
    const float* sc = (const float*)d_in[2];
    float* out = (float*)d_out;

    cudaFuncSetAttribute(enc_kernel, cudaFuncAttributeMaxDynamicSharedMemorySize, SMEM_TOTAL);

    int n4 = out_size / 4;                 // 16384 float4
    zero_kernel<<<(n4 + 255) / 256, 256>>>((float4*)out, n4);

    dim3 grid(CHUNKS, BB);
    enc_kernel<<<grid, NTHREADS, SMEM_TOTAL>>>(x, cw, sc, out);
}